// round 15
// baseline (speedup 1.0000x reference)
#include <cuda_runtime.h>

#define IMGS 16
#define HH 1024
#define WW 1024
#define WORDS 32                     // 32-bit words per row
#define NWORDS (IMGS*HH*WORDS)       // 524288
#define NPIX   (IMGS*HH*WW)          // 16777216
#define STRIP 4
#define NPART 512                    // fused blocks (= partials)

__device__ __align__(16) unsigned g_bits[NWORDS];  // binarized target
__device__ float    g_part[NPART];
__device__ unsigned g_count = 0;

// ---------------- K0: binarize target into bitmask (LDG.128 + shfl merge) ---
// One WARP covers 1024 contiguous pixels: 8 front-batched uint4 loads/lane.
// target is exactly 0.0f (0x00000000) or 1.0f (0x3F800000): bit 29 is the
// discriminating bit.
__global__ __launch_bounds__(256) void k_binarize(const uint4* __restrict__ tgt) {
    unsigned warpId = (blockIdx.x * blockDim.x + threadIdx.x) >> 5;  // 0..16383
    unsigned lane = threadIdx.x & 31;
    const uint4* base = tgt + warpId * 256 + lane;   // uint4 units
    uint4 u[8];
    #pragma unroll
    for (int c = 0; c < 8; c++) u[c] = base[c * 32];
    #pragma unroll
    for (int c = 0; c < 8; c++) {
        unsigned nib = ((u[c].x >> 29) & 1u) | ((u[c].y >> 28) & 2u)
                     | ((u[c].z >> 27) & 4u) | ((u[c].w >> 26) & 8u);
        nib |= __shfl_down_sync(0xffffffffu, nib, 1) << 4;
        nib |= __shfl_down_sync(0xffffffffu, nib, 2) << 8;
        nib |= __shfl_down_sync(0xffffffffu, nib, 4) << 16;
        if ((lane & 7u) == 0u)
            g_bits[warpId * 32 + c * 4 + (lane >> 3)] = nib;
    }
}

// ---------------- bit-slice helpers (warp = one 1024-col row) ----------------
__device__ __forceinline__ unsigned shLr(unsigned v, int lane) {       // replicate at col 0
    unsigned up = __shfl_up_sync(0xffffffffu, v, 1);
    unsigned carry = (lane == 0) ? (v & 1u) : (up >> 31);
    return (v << 1) | carry;
}
__device__ __forceinline__ unsigned shLz(unsigned v, int lane) {       // zero at col 0
    unsigned up = __shfl_up_sync(0xffffffffu, v, 1);
    unsigned carry = (lane == 0) ? 0u : (up >> 31);
    return (v << 1) | carry;
}
__device__ __forceinline__ unsigned shRr(unsigned v, int lane) {       // replicate at col W-1
    unsigned dn = __shfl_down_sync(0xffffffffu, v, 1);
    unsigned carry = (lane == 31) ? (v >> 31) : (dn & 1u);
    return (v >> 1) | (carry << 31);
}
__device__ __forceinline__ unsigned shRz(unsigned v, int lane) {       // zero at col W-1
    unsigned dn = __shfl_down_sync(0xffffffffu, v, 1);
    unsigned carry = (lane == 31) ? 0u : (dn & 1u);
    return (v >> 1) | (carry << 31);
}

// rowsum r = img[x-1] + 2*img[x] + img[x+1]  (0..4, 3 planes), edge-replicate
__device__ __forceinline__ void rowsum(unsigned Bv, int lane, unsigned r[3]) {
    unsigned L = shLr(Bv, lane), R = shRr(Bv, lane);
    unsigned s = L ^ R, c = L & R;
    r[0] = s; r[1] = Bv ^ c; r[2] = Bv & c;
}

struct S3 { unsigned a0, a1, a2, sg, nz; };      // |x-y| (0..4), sign, nonzero

__device__ __forceinline__ S3 sub3(const unsigned x[3], const unsigned y[3]) {
    unsigned ny0 = ~y[0], ny1 = ~y[1], ny2 = ~y[2];
    unsigned cin = 0xffffffffu;
    unsigned t0 = x[0] ^ ny0, d0 = t0 ^ cin, c1 = (x[0] & ny0) | (cin & t0);
    unsigned t1 = x[1] ^ ny1, d1 = t1 ^ c1,  c2 = (x[1] & ny1) | (c1 & t1);
    unsigned t2 = x[2] ^ ny2, d2 = t2 ^ c2,  c3 = (x[2] & ny2) | (c2 & t2);
    unsigned sg = ~c3;                           // sign plane (negative)
    unsigned e0 = d0 ^ sg, e1 = d1 ^ sg, e2 = d2 ^ sg;  // conditional negate
    S3 r;
    r.a0 = e0 ^ sg; unsigned cc = e0 & sg;
    r.a1 = e1 ^ cc; cc = e1 & cc;
    r.a2 = e2 ^ cc;
    r.sg = sg;
    r.nz = r.a0 | r.a1 | r.a2;
    return r;
}

__device__ __forceinline__ void add3(const S3& x, const S3& y, unsigned m[4]) {
    unsigned c;
    m[0] = x.a0 ^ y.a0; c = x.a0 & y.a0;
    unsigned t = x.a1 ^ y.a1; m[1] = t ^ c; c = (x.a1 & y.a1) | (c & t);
    t = x.a2 ^ y.a2; m[2] = t ^ c; c = (x.a2 & y.a2) | (c & t);
    m[3] = c;
}

__device__ __forceinline__ unsigned gt4(const unsigned x[4], const unsigned y[4]) {
    unsigned g = x[0] & ~y[0];
    g = (x[1] & ~y[1]) | (~(x[1] ^ y[1]) & g);
    g = (x[2] & ~y[2]) | (~(x[2] ^ y[2]) & g);
    g = (x[3] & ~y[3]) | (~(x[3] ^ y[3]) & g);
    return g;
}

// ---------------- K1: fused strip cand (NMS + 5x5 dilate) + BCE -------------
// Warp = 4-row strip of one image (4096 warps, 512 blocks). The validated
// strip pipeline (10 iterations for 4 output rows) captures per-row registers:
//   tbrow[r] = target bitmask word of row r0+r (B0 when t == r0+r)
//   w5row[r] = OR of 5 horizontally-dilated cand rows = 5x5-dilated edge zone
// then BCE for the 4 rows with masks distributed via shfl (R14-validated).
__global__ __launch_bounds__(256) void k_fused(const float4* __restrict__ pred,
                                               float* __restrict__ out) {
    int lane = threadIdx.x & 31;
    int warp = (blockIdx.x * blockDim.x + threadIdx.x) >> 5;
    int im = warp >> 8;                          // image (256 strips per image)
    int r0 = (warp & 255) << 2;                  // strip base row
    const unsigned* bits = g_bits + im * HH * WORDS;

    unsigned colMask = 0xffffffffu;
    if (lane == 0)  colMask &= ~1u;
    if (lane == 31) colMask &= 0x7fffffffu;

    auto loadB = [&](int y) -> unsigned {
        y = y < 0 ? 0 : (y > HH - 1 ? HH - 1 : y);
        return bits[y * WORDS + lane];
    };

    const int tF = r0 - 3;                       // 10 iterations: t = tF..r0+6
    unsigned Bm1 = loadB(tF - 1), B0 = loadB(tF), Bp1 = loadB(tF + 1);
    unsigned rm1[3], rcn[3], rp1[3];
    rowsum(Bm1, lane, rm1); rowsum(B0, lane, rcn); rowsum(Bp1, lane, rp1);

    unsigned mA[4] = {0,0,0,0}, mAL[4] = {0,0,0,0}, mAR[4] = {0,0,0,0};
    unsigned mB[4] = {0,0,0,0}, mBL[4] = {0,0,0,0}, mBR[4] = {0,0,0,0};
    unsigned Hc = 0, Vc = 0, Sc = 0, Ec = 0;
    unsigned h0 = 0, h1 = 0, h2 = 0, h3 = 0, h4 = 0;
    unsigned tbrow[STRIP], w5row[STRIP];

    #pragma unroll
    for (int ti = 0; ti < STRIP + 6; ti++) {
        int t = tF + ti;                         // ti: t - r0 = ti - 3
        if (ti >= 3 && ti < 3 + STRIP) tbrow[ti - 3] = B0;   // B0 == bits[t]

        unsigned s = Bm1 ^ Bp1, cr = Bm1 & Bp1;
        unsigned v[3]  = { s, B0 ^ cr, B0 & cr };
        unsigned vL[3] = { shLr(v[0], lane), shLr(v[1], lane), shLr(v[2], lane) };
        unsigned vR[3] = { shRr(v[0], lane), shRr(v[1], lane), shRr(v[2], lane) };
        S3 ax = sub3(vR, vL);        // |gx|, sign(gx)
        S3 ay = sub3(rp1, rm1);      // |gy|, sign(gy)
        unsigned mC[4]; add3(ax, ay, mC);
        unsigned mCL[4], mCR[4];
        #pragma unroll
        for (int k = 0; k < 4; k++) {
            mCL[k] = shLz(mC[k], lane);
            mCR[k] = shRz(mC[k], lane);
        }

        unsigned nzx = ax.nz, nzy = ay.nz;
        unsigned ay0   = ~nzy;
        unsigned ayle1 = ~(ay.a1 | ay.a2);
        unsigned axge3 = ax.a2 | (ax.a1 & ax.a0);
        unsigned horiz = (nzx & ay0) | (axge3 & ayle1);
        unsigned ax0m  = ~nzx;
        unsigned ax1m  = ax.a0 & ~ax.a1 & ~ax.a2;
        unsigned ayge3 = ay.a2 | (ay.a1 & ay.a0);
        unsigned vertm = (ax0m & nzy) | (ax1m & ayge3);
        unsigned sd    = (ax.sg ^ ay.sg) & nzx & nzy;
        unsigned nh = ~horiz;
        unsigned Hn = horiz;
        unsigned Vn = nh & vertm;
        unsigned tq = nh & ~vertm;
        unsigned Sn = tq & sd;
        unsigned En = tq & ~sd;

        if (ti >= 2) {
            int c = t - 1;                       // center (cand) row
            unsigned n1[4], n2[4];
            #pragma unroll
            for (int k = 0; k < 4; k++) {
                n1[k] = (Hc & mBL[k]) | (Vc & mA[k]) | (Sc & mAR[k]) | (Ec & mAL[k]);
                n2[k] = (Hc & mBR[k]) | (Vc & mC[k]) | (Sc & mCL[k]) | (Ec & mCR[k]);
            }
            unsigned keep = gt4(mB, n1) & ~gt4(n2, mB);
            unsigned mnz  = mB[0] | mB[1] | mB[2] | mB[3];   // m>50 <=> m_int>=1
            unsigned cand = keep & mnz & colMask;
            if (c < 1 || c > HH - 2) cand = 0;               // interior rows only

            unsigned l1 = shLz(cand, lane), l2 = shLz(l1, lane);
            unsigned q1 = shRz(cand, lane), q2 = shRz(q1, lane);
            unsigned h = cand | l1 | l2 | q1 | q2;
            h0 = h1; h1 = h2; h2 = h3; h3 = h4; h4 = h;

            int r = t - 3 - r0;                  // cOut - r0, ti-6..  (cOut = c-2)
            if (r >= 0 && r < STRIP)
                w5row[r] = h0 | h1 | h2 | h3 | h4;
        }

        #pragma unroll
        for (int k = 0; k < 4; k++) {
            mA[k] = mB[k]; mAL[k] = mBL[k]; mAR[k] = mBR[k];
            mB[k] = mC[k]; mBL[k] = mCL[k]; mBR[k] = mCR[k];
        }
        Hc = Hn; Vc = Vn; Sc = Sn; Ec = En;
        Bm1 = B0; B0 = Bp1; Bp1 = loadB(t + 2);
        rm1[0] = rcn[0]; rm1[1] = rcn[1]; rm1[2] = rcn[2];
        rcn[0] = rp1[0]; rcn[1] = rp1[1]; rcn[2] = rp1[2];
        rowsum(Bp1, lane, rp1);
    }

    // ---- BCE for rows r0..r0+3 (masks from registers via shfl) ----
    int sh = (lane & 7) * 4;
    int srcLane0 = lane >> 3;                    // word index base for chunks
    float s0 = 0.f, s1 = 0.f, s2 = 0.f, s3 = 0.f;
    #pragma unroll
    for (int r = 0; r < STRIP; r++) {
        unsigned rowBase4 = (unsigned)(im * HH + r0 + r) * 256u;  // float4 units
        float4 p[8];
        #pragma unroll
        for (int k = 0; k < 8; k++) p[k] = pred[rowBase4 + lane + 32 * k];
        #pragma unroll
        for (int k = 0; k < 8; k++) {
            unsigned trk = __shfl_sync(0xffffffffu, tbrow[r], 4 * k + srcLane0);
            unsigned wmk = __shfl_sync(0xffffffffu, w5row[r], 4 * k + srcLane0);
            unsigned t = trk >> sh, m = wmk >> sh;
            float a0 = (t & 1u) ? p[k].x : 1.0f - p[k].x;
            float a1 = (t & 2u) ? p[k].y : 1.0f - p[k].y;
            float a2 = (t & 4u) ? p[k].z : 1.0f - p[k].z;
            float a3 = (t & 8u) ? p[k].w : 1.0f - p[k].w;
            float w0 = (m & 1u) ? 5.0f : 1.0f;
            float w1 = (m & 2u) ? 5.0f : 1.0f;
            float w2 = (m & 4u) ? 5.0f : 1.0f;
            float w3 = (m & 8u) ? 5.0f : 1.0f;
            s0 -= w0 * __logf(a0);
            s1 -= w1 * __logf(a1);
            s2 -= w2 * __logf(a2);
            s3 -= w3 * __logf(a3);
        }
    }
    float s = (s0 + s1) + (s2 + s3);

    #pragma unroll
    for (int off = 16; off > 0; off >>= 1) s += __shfl_down_sync(0xffffffffu, s, off);
    __shared__ float wsum[8];
    if (lane == 0) wsum[threadIdx.x >> 5] = s;
    __syncthreads();
    __shared__ bool amLast;
    if (threadIdx.x == 0) {
        float tsum = 0.f;
        #pragma unroll
        for (int k = 0; k < 8; k++) tsum += wsum[k];
        g_part[blockIdx.x] = tsum;
        __threadfence();
        unsigned prev = atomicAdd(&g_count, 1u);
        amLast = (prev == NPART - 1);
    }
    __syncthreads();

    if (amLast) {
        __threadfence();
        __shared__ double dsm[256];
        double d = 0.0;
        #pragma unroll
        for (int k = 0; k < NPART / 256; k++)
            d += (double)g_part[threadIdx.x + k * 256];
        dsm[threadIdx.x] = d;
        __syncthreads();
        for (int off = 128; off > 0; off >>= 1) {
            if (threadIdx.x < off) dsm[threadIdx.x] += dsm[threadIdx.x + off];
            __syncthreads();
        }
        if (threadIdx.x == 0) {
            out[0] = (float)(dsm[0] / (double)NPIX);
            g_count = 0;                          // reset for next graph replay
        }
    }
}

extern "C" void kernel_launch(void* const* d_in, const int* in_sizes, int n_in,
                              void* d_out, int out_size) {
    (void)in_sizes; (void)n_in; (void)out_size;
    const float* pred = (const float*)d_in[0];
    const float* tgt  = (const float*)d_in[1];
    k_binarize<<<NPIX / 8192, 256>>>((const uint4*)tgt);   // 2048 blocks
    k_fused<<<NPART, 256>>>((const float4*)pred, (float*)d_out);
}

// round 17
// speedup vs baseline: 1.5964x; 1.5964x over previous
#include <cuda_runtime.h>

#define IMGS 16
#define HH 1024
#define WW 1024
#define WORDS 32                     // 32-bit words per row
#define NPIX   (IMGS*HH*WW)          // 16777216
#define STRIP 4                      // rows per warp
#define BROWS 32                     // rows per block (8 warps)
#define HROWS 41                     // strip + halo rows in smem (r0-4 .. r0+36)
#define NPART 512                    // blocks (= partials)

__device__ float    g_part[NPART];
__device__ unsigned g_count = 0;

// ---------------- bit-slice helpers (warp = one 1024-col row) ----------------
__device__ __forceinline__ unsigned shLr(unsigned v, int lane) {       // replicate at col 0
    unsigned up = __shfl_up_sync(0xffffffffu, v, 1);
    unsigned carry = (lane == 0) ? (v & 1u) : (up >> 31);
    return (v << 1) | carry;
}
__device__ __forceinline__ unsigned shLz(unsigned v, int lane) {       // zero at col 0
    unsigned up = __shfl_up_sync(0xffffffffu, v, 1);
    unsigned carry = (lane == 0) ? 0u : (up >> 31);
    return (v << 1) | carry;
}
__device__ __forceinline__ unsigned shRr(unsigned v, int lane) {       // replicate at col W-1
    unsigned dn = __shfl_down_sync(0xffffffffu, v, 1);
    unsigned carry = (lane == 31) ? (v >> 31) : (dn & 1u);
    return (v >> 1) | (carry << 31);
}
__device__ __forceinline__ unsigned shRz(unsigned v, int lane) {       // zero at col W-1
    unsigned dn = __shfl_down_sync(0xffffffffu, v, 1);
    unsigned carry = (lane == 31) ? 0u : (dn & 1u);
    return (v >> 1) | (carry << 31);
}

// rowsum r = img[x-1] + 2*img[x] + img[x+1]  (0..4, 3 planes), edge-replicate
__device__ __forceinline__ void rowsum(unsigned Bv, int lane, unsigned r[3]) {
    unsigned L = shLr(Bv, lane), R = shRr(Bv, lane);
    unsigned s = L ^ R, c = L & R;
    r[0] = s; r[1] = Bv ^ c; r[2] = Bv & c;
}

struct S3 { unsigned a0, a1, a2, sg, nz; };      // |x-y| (0..4), sign, nonzero

__device__ __forceinline__ S3 sub3(const unsigned x[3], const unsigned y[3]) {
    unsigned ny0 = ~y[0], ny1 = ~y[1], ny2 = ~y[2];
    unsigned cin = 0xffffffffu;
    unsigned t0 = x[0] ^ ny0, d0 = t0 ^ cin, c1 = (x[0] & ny0) | (cin & t0);
    unsigned t1 = x[1] ^ ny1, d1 = t1 ^ c1,  c2 = (x[1] & ny1) | (c1 & t1);
    unsigned t2 = x[2] ^ ny2, d2 = t2 ^ c2,  c3 = (x[2] & ny2) | (c2 & t2);
    unsigned sg = ~c3;                           // sign plane (negative)
    unsigned e0 = d0 ^ sg, e1 = d1 ^ sg, e2 = d2 ^ sg;  // conditional negate
    S3 r;
    r.a0 = e0 ^ sg; unsigned cc = e0 & sg;
    r.a1 = e1 ^ cc; cc = e1 & cc;
    r.a2 = e2 ^ cc;
    r.sg = sg;
    r.nz = r.a0 | r.a1 | r.a2;
    return r;
}

__device__ __forceinline__ void add3(const S3& x, const S3& y, unsigned m[4]) {
    unsigned c;
    m[0] = x.a0 ^ y.a0; c = x.a0 & y.a0;
    unsigned t = x.a1 ^ y.a1; m[1] = t ^ c; c = (x.a1 & y.a1) | (c & t);
    t = x.a2 ^ y.a2; m[2] = t ^ c; c = (x.a2 & y.a2) | (c & t);
    m[3] = c;
}

__device__ __forceinline__ unsigned gt4(const unsigned x[4], const unsigned y[4]) {
    unsigned g = x[0] & ~y[0];
    g = (x[1] & ~y[1]) | (~(x[1] ^ y[1]) & g);
    g = (x[2] & ~y[2]) | (~(x[2] ^ y[2]) & g);
    g = (x[3] & ~y[3]) | (~(x[3] ^ y[3]) & g);
    return g;
}

// ---------------- single fused kernel: binarize(smem) + cand + BCE ----------
// Block = 8 warps = 32-row strip of one image (512 blocks).
// Phase 1: binarize rows r0-4 .. r0+36 (image-clamped) into smem, using the
//          proven uint4-load + shfl-nibble-merge packer (bit 29 discriminates
//          0x3F800000 from 0x00000000).
// Phase 2: per warp, the validated 10-iteration strip pipeline for rows
//          r0w..r0w+3, loadB served from smem; captures tbrow[] and w5row[].
// Phase 3: validated BCE with shfl mask distribution + deterministic
//          last-block reduction.
__global__ __launch_bounds__(256) void k_all(const float4* __restrict__ pred,
                                             const uint4* __restrict__ tgt,
                                             float* __restrict__ out) {
    __shared__ unsigned sb[HROWS * WORDS];       // 41 x 32 words = 5.1 KB
    int lane = threadIdx.x & 31;
    int w = threadIdx.x >> 5;                    // warp in block (0..7)
    int im = blockIdx.x >> 5;                    // image (32 strips per image)
    int r0 = (blockIdx.x & 31) << 5;             // block strip base row

    // ---- Phase 1: binarize halo'd strip into smem ----
    for (int j = w; j < HROWS; j += 8) {
        int y = r0 - 4 + j;
        y = y < 0 ? 0 : (y > HH - 1 ? HH - 1 : y);
        const uint4* base = tgt + (unsigned)(im * HH + y) * 64u + lane;  // uint4 units (256/row)
        uint4 u[8];
        #pragma unroll
        for (int c = 0; c < 8; c++) u[c] = base[c * 32];
        #pragma unroll
        for (int c = 0; c < 8; c++) {
            unsigned nib = ((u[c].x >> 29) & 1u) | ((u[c].y >> 28) & 2u)
                         | ((u[c].z >> 27) & 4u) | ((u[c].w >> 26) & 8u);
            nib |= __shfl_down_sync(0xffffffffu, nib, 1) << 4;
            nib |= __shfl_down_sync(0xffffffffu, nib, 2) << 8;
            nib |= __shfl_down_sync(0xffffffffu, nib, 4) << 16;
            if ((lane & 7) == 0)
                sb[j * WORDS + c * 4 + (lane >> 3)] = nib;
        }
    }
    __syncthreads();

    // ---- Phase 2: strip pipeline (rows r0w..r0w+3) ----
    int r0w = r0 + w * STRIP;                    // this warp's strip base
    unsigned colMask = 0xffffffffu;
    if (lane == 0)  colMask &= ~1u;
    if (lane == 31) colMask &= 0x7fffffffu;

    auto loadB = [&](int y) -> unsigned {        // smem-served, image-clamped
        y = y < 0 ? 0 : (y > HH - 1 ? HH - 1 : y);
        return sb[(y - r0 + 4) * WORDS + lane];
    };

    const int tF = r0w - 3;                      // 10 iterations: t = tF..r0w+6
    unsigned Bm1 = loadB(tF - 1), B0 = loadB(tF), Bp1 = loadB(tF + 1);
    unsigned rm1[3], rcn[3], rp1[3];
    rowsum(Bm1, lane, rm1); rowsum(B0, lane, rcn); rowsum(Bp1, lane, rp1);

    unsigned mA[4] = {0,0,0,0}, mAL[4] = {0,0,0,0}, mAR[4] = {0,0,0,0};
    unsigned mB[4] = {0,0,0,0}, mBL[4] = {0,0,0,0}, mBR[4] = {0,0,0,0};
    unsigned Hc = 0, Vc = 0, Sc = 0, Ec = 0;
    unsigned h0 = 0, h1 = 0, h2 = 0, h3 = 0, h4 = 0;
    unsigned tbrow[STRIP], w5row[STRIP];

    #pragma unroll
    for (int ti = 0; ti < STRIP + 6; ti++) {
        int t = tF + ti;                         // t - r0w = ti - 3
        if (ti >= 3 && ti < 3 + STRIP) tbrow[ti - 3] = B0;   // B0 == bits[t]

        unsigned s = Bm1 ^ Bp1, cr = Bm1 & Bp1;
        unsigned v[3]  = { s, B0 ^ cr, B0 & cr };
        unsigned vL[3] = { shLr(v[0], lane), shLr(v[1], lane), shLr(v[2], lane) };
        unsigned vR[3] = { shRr(v[0], lane), shRr(v[1], lane), shRr(v[2], lane) };
        S3 ax = sub3(vR, vL);        // |gx|, sign(gx)
        S3 ay = sub3(rp1, rm1);      // |gy|, sign(gy)
        unsigned mC[4]; add3(ax, ay, mC);
        unsigned mCL[4], mCR[4];
        #pragma unroll
        for (int k = 0; k < 4; k++) {
            mCL[k] = shLz(mC[k], lane);
            mCR[k] = shRz(mC[k], lane);
        }

        unsigned nzx = ax.nz, nzy = ay.nz;
        unsigned ay0   = ~nzy;
        unsigned ayle1 = ~(ay.a1 | ay.a2);
        unsigned axge3 = ax.a2 | (ax.a1 & ax.a0);
        unsigned horiz = (nzx & ay0) | (axge3 & ayle1);
        unsigned ax0m  = ~nzx;
        unsigned ax1m  = ax.a0 & ~ax.a1 & ~ax.a2;
        unsigned ayge3 = ay.a2 | (ay.a1 & ay.a0);
        unsigned vertm = (ax0m & nzy) | (ax1m & ayge3);
        unsigned sd    = (ax.sg ^ ay.sg) & nzx & nzy;
        unsigned nh = ~horiz;
        unsigned Hn = horiz;
        unsigned Vn = nh & vertm;
        unsigned tq = nh & ~vertm;
        unsigned Sn = tq & sd;
        unsigned En = tq & ~sd;

        if (ti >= 2) {
            int c = t - 1;                       // center (cand) row
            unsigned n1[4], n2[4];
            #pragma unroll
            for (int k = 0; k < 4; k++) {
                n1[k] = (Hc & mBL[k]) | (Vc & mA[k]) | (Sc & mAR[k]) | (Ec & mAL[k]);
                n2[k] = (Hc & mBR[k]) | (Vc & mC[k]) | (Sc & mCL[k]) | (Ec & mCR[k]);
            }
            unsigned keep = gt4(mB, n1) & ~gt4(n2, mB);
            unsigned mnz  = mB[0] | mB[1] | mB[2] | mB[3];   // m>50 <=> m_int>=1
            unsigned cand = keep & mnz & colMask;
            if (c < 1 || c > HH - 2) cand = 0;               // interior rows only

            unsigned l1 = shLz(cand, lane), l2 = shLz(l1, lane);
            unsigned q1 = shRz(cand, lane), q2 = shRz(q1, lane);
            unsigned h = cand | l1 | l2 | q1 | q2;
            h0 = h1; h1 = h2; h2 = h3; h3 = h4; h4 = h;

            int r = t - 3 - r0w;                 // output row index (cOut = c-2)
            if (r >= 0 && r < STRIP)
                w5row[r] = h0 | h1 | h2 | h3 | h4;
        }

        #pragma unroll
        for (int k = 0; k < 4; k++) {
            mA[k] = mB[k]; mAL[k] = mBL[k]; mAR[k] = mBR[k];
            mB[k] = mC[k]; mBL[k] = mCL[k]; mBR[k] = mCR[k];
        }
        Hc = Hn; Vc = Vn; Sc = Sn; Ec = En;
        Bm1 = B0; B0 = Bp1; Bp1 = loadB(t + 2);
        rm1[0] = rcn[0]; rm1[1] = rcn[1]; rm1[2] = rcn[2];
        rcn[0] = rp1[0]; rcn[1] = rp1[1]; rcn[2] = rp1[2];
        rowsum(Bp1, lane, rp1);
    }

    // ---- Phase 3: BCE for rows r0w..r0w+3 (masks via shfl) ----
    int sh = (lane & 7) * 4;
    int srcLane0 = lane >> 3;
    float s0 = 0.f, s1 = 0.f, s2 = 0.f, s3 = 0.f;
    #pragma unroll
    for (int r = 0; r < STRIP; r++) {
        unsigned rowBase4 = (unsigned)(im * HH + r0w + r) * 256u;  // float4 units
        float4 p[8];
        #pragma unroll
        for (int k = 0; k < 8; k++) p[k] = pred[rowBase4 + lane + 32 * k];
        #pragma unroll
        for (int k = 0; k < 8; k++) {
            unsigned trk = __shfl_sync(0xffffffffu, tbrow[r], 4 * k + srcLane0);
            unsigned wmk = __shfl_sync(0xffffffffu, w5row[r], 4 * k + srcLane0);
            unsigned t = trk >> sh, m = wmk >> sh;
            float a0 = (t & 1u) ? p[k].x : 1.0f - p[k].x;
            float a1 = (t & 2u) ? p[k].y : 1.0f - p[k].y;
            float a2 = (t & 4u) ? p[k].z : 1.0f - p[k].z;
            float a3 = (t & 8u) ? p[k].w : 1.0f - p[k].w;
            float w0 = (m & 1u) ? 5.0f : 1.0f;
            float w1 = (m & 2u) ? 5.0f : 1.0f;
            float w2 = (m & 4u) ? 5.0f : 1.0f;
            float w3 = (m & 8u) ? 5.0f : 1.0f;
            s0 -= w0 * __logf(a0);
            s1 -= w1 * __logf(a1);
            s2 -= w2 * __logf(a2);
            s3 -= w3 * __logf(a3);
        }
    }
    float s = (s0 + s1) + (s2 + s3);

    #pragma unroll
    for (int off = 16; off > 0; off >>= 1) s += __shfl_down_sync(0xffffffffu, s, off);
    __shared__ float wsum[8];
    if (lane == 0) wsum[w] = s;
    __syncthreads();
    __shared__ bool amLast;
    if (threadIdx.x == 0) {
        float tsum = 0.f;
        #pragma unroll
        for (int k = 0; k < 8; k++) tsum += wsum[k];
        g_part[blockIdx.x] = tsum;
        __threadfence();
        unsigned prev = atomicAdd(&g_count, 1u);
        amLast = (prev == NPART - 1);
    }
    __syncthreads();

    if (amLast) {
        __threadfence();
        __shared__ double dsm[256];
        double d = 0.0;
        #pragma unroll
        for (int k = 0; k < NPART / 256; k++)
            d += (double)g_part[threadIdx.x + k * 256];
        dsm[threadIdx.x] = d;
        __syncthreads();
        for (int off = 128; off > 0; off >>= 1) {
            if (threadIdx.x < off) dsm[threadIdx.x] += dsm[threadIdx.x + off];
            __syncthreads();
        }
        if (threadIdx.x == 0) {
            out[0] = (float)(dsm[0] / (double)NPIX);
            g_count = 0;                          // reset for next graph replay
        }
    }
}

extern "C" void kernel_launch(void* const* d_in, const int* in_sizes, int n_in,
                              void* d_out, int out_size) {
    (void)in_sizes; (void)n_in; (void)out_size;
    const float* pred = (const float*)d_in[0];
    const float* tgt  = (const float*)d_in[1];
    k_all<<<NPART, 256>>>((const float4*)pred, (const uint4*)tgt, (float*)d_out);
}